// round 3
// baseline (speedup 1.0000x reference)
#include <cuda_runtime.h>
#include <cstdint>

#define TSTEPS 512
#define BSZ    256
#define DIN    128
#define HID    256
#define NPROTO 128
#define DHTOT  384
#define NB     8            // batches per cluster
#define CSZ    4            // CTAs per cluster
#define NTHR   512
#define NCTA   (BSZ / NB * CSZ)   // 128

// Preprocessed weight layouts (device scratch — no allocation).
__device__ float4 g_Wpack[NPROTO][HID];          // [p][h] = {wf, wi, wg, wo}
__device__ float4 g_protoPack[DHTOT/4][NPROTO];  // [q][p] = proto[p][4q..4q+3]
__device__ float  g_pn2[NPROTO];

typedef unsigned long long u64;

// ---------------- smem layout (dynamic) ----------------
// WQ  : [128 p][64 h_local] float4          131072
// COMB: [4 pair][384 d] u64 ({b_even,b_odd}) 12288
// KD  : [128 p][8 b] u64 ({k,k})              8192
// PG  : [8 pc][8 b][2 fi][64 h] u64          65536   (PD aliases first 16KB)
// PD  : [16 dc][4 pair][32 pl] u64           16384   (alias @ PG)
// CN  : [4 pair] u64                            32
#define WQ_OFF    0
#define COMB_OFF  131072
#define KD_OFF    143360
#define PG_OFF    151552
#define PD_OFF    151552
#define CN_OFF    217088
#define SMEM_TOTAL 217120

__device__ __forceinline__ u64 pk2(float lo, float hi){
    u64 r; asm("mov.b64 %0, {%1,%2};" : "=l"(r) : "f"(lo), "f"(hi)); return r;
}
__device__ __forceinline__ void upk2(u64 v, float& lo, float& hi){
    asm("mov.b64 {%0,%1}, %2;" : "=f"(lo), "=f"(hi) : "l"(v));
}
__device__ __forceinline__ u64 ffma2(u64 a, u64 b, u64 c){
    u64 d; asm("fma.rn.f32x2 %0, %1, %2, %3;" : "=l"(d) : "l"(a), "l"(b), "l"(c)); return d;
}
__device__ __forceinline__ u64 add2(u64 a, u64 b){
    u64 d; asm("add.rn.f32x2 %0, %1, %2;" : "=l"(d) : "l"(a), "l"(b)); return d;
}
__device__ __forceinline__ float sigmf(float x){
    return __fdividef(1.f, 1.f + __expf(-x));
}
__device__ __forceinline__ float tanhf_(float x){
    return 1.f - __fdividef(2.f, __expf(2.f*x) + 1.f);
}
__device__ __forceinline__ uint32_t smem_u32(const void* p){
    uint32_t a;
    asm("{ .reg .u64 t; cvta.to.shared.u64 t, %1; cvt.u32.u64 %0, t; }" : "=r"(a) : "l"(p));
    return a;
}
__device__ __forceinline__ uint32_t ctarank(){
    uint32_t r; asm("mov.u32 %0, %%cluster_ctarank;" : "=r"(r)); return r;
}
__device__ __forceinline__ uint32_t mapa_u32(uint32_t local, uint32_t rank){
    uint32_t r; asm("mapa.shared::cluster.u32 %0, %1, %2;" : "=r"(r) : "r"(local), "r"(rank));
    return r;
}
__device__ __forceinline__ void st_cl64(uint32_t addr, u64 v){
    asm volatile("st.shared::cluster.b64 [%0], %1;" :: "r"(addr), "l"(v) : "memory");
}
__device__ __forceinline__ void st_cl32(uint32_t addr, float v){
    asm volatile("st.shared::cluster.b32 [%0], %1;" :: "r"(addr), "f"(v) : "memory");
}
__device__ __forceinline__ void cl_arrive(){
    asm volatile("barrier.cluster.arrive.aligned;" ::: "memory");
}
__device__ __forceinline__ void cl_wait(){
    asm volatile("barrier.cluster.wait.aligned;"   ::: "memory");
}

__global__ void pack_kernel(const float* __restrict__ proto,
                            const float* __restrict__ Wf, const float* __restrict__ Wi,
                            const float* __restrict__ Wg, const float* __restrict__ Wo){
    int idx = blockIdx.x * blockDim.x + threadIdx.x;
    if (idx < HID*NPROTO){
        int h = idx >> 7, pp = idx & (NPROTO-1);
        g_Wpack[pp][h] = make_float4(Wf[idx], Wi[idx], Wg[idx], Wo[idx]);
    }
    if (idx < (DHTOT/4)*NPROTO){
        int q = idx >> 7, pp = idx & (NPROTO-1);
        const float* pr = proto + pp*DHTOT + 4*q;
        g_protoPack[q][pp] = make_float4(pr[0], pr[1], pr[2], pr[3]);
    }
    if (idx < NPROTO){
        float s = 0.f;
        for (int d = 0; d < DHTOT; ++d){ float v = proto[idx*DHTOT + d]; s = fmaf(v, v, s); }
        g_pn2[idx] = s;
    }
}

extern __shared__ char sm[];

__global__ void __cluster_dims__(CSZ,1,1) __launch_bounds__(NTHR, 1)
qlstm_kernel(const float* __restrict__ x,
             const float* __restrict__ bf, const float* __restrict__ bi,
             const float* __restrict__ bg, const float* __restrict__ bo,
             float* __restrict__ out){
    const int tid  = threadIdx.x;
    const uint32_t rank = ctarank();
    const int bbase = (blockIdx.x >> 2) * NB;
    const uint32_t base = smem_u32(sm);

    float4*     WQ    = reinterpret_cast<float4*>(sm + WQ_OFF);
    u64*        COMB  = reinterpret_cast<u64*>(sm + COMB_OFF);
    float*      COMBF = reinterpret_cast<float*>(sm + COMB_OFF);
    u64*        KD    = reinterpret_cast<u64*>(sm + KD_OFF);
    const ulonglong2* KD2 = reinterpret_cast<const ulonglong2*>(sm + KD_OFF);
    u64*        PG    = reinterpret_cast<u64*>(sm + PG_OFF);
    u64*        PD    = reinterpret_cast<u64*>(sm + PD_OFF);
    u64*        CN    = reinterpret_cast<u64*>(sm + CN_OFF);

    // ---- preamble: fill weight quarter into smem ----
    {
        const float4* src = &g_Wpack[0][rank*64];
        #pragma unroll
        for (int i = 0; i < (NPROTO*64)/NTHR; ++i){
            int idx = tid + i*NTHR;
            int p  = idx >> 6, hl = idx & 63;
            WQ[idx] = src[p*HID + hl];
        }
    }
    // zero hx region of comb (4 pairs x 256 d = 1024 u64)
    #pragma unroll
    for (int i = 0; i < 2; ++i){
        int idx = tid + i*NTHR;
        COMB[(idx >> 8)*DHTOT + DIN + (idx & 255)] = 0ull;
    }
    // load x(0)
    {
        const float* xb = x + (size_t)bbase*DIN;
        #pragma unroll
        for (int i = 0; i < (NB*DIN)/NTHR; ++i){
            int idx = tid + i*NTHR;
            int b = idx >> 7, d = idx & (DIN-1);
            COMBF[(b >> 1)*DHTOT*2 + d*2 + (b & 1)] = __ldcg(&xb[idx]);
        }
    }

    // per-thread constants
    const int hL    = tid & 63;                   // gate/reduce h_local
    const int pcG   = tid >> 6;                   // gate pchunk (0..7) / reduce batch
    const int bbR   = pcG;                        // reduce: batch index 0..7
    const int hglob = rank*64 + hL;
    const u64 bFI   = pk2(bf[hglob], bi[hglob]);
    const u64 bGO   = pk2(bg[hglob], bo[hglob]);

    const int plD = tid & 31;                     // dist p_local
    const int dcD = tid >> 5;                     // dist d-chunk (0..15), 24 d each
    const float pn2v = g_pn2[rank*32 + plD];      // valid when tid<128

    // hoisted DSMEM addresses
    uint32_t kAddr[CSZ], hvAddr[CSZ];
    {
        uint32_t koff = base + KD_OFF + (uint32_t)(((rank*32 + plD)*8 + 2*(tid>>5))*8);
        // hv for (batch bbR, h hglob): COMB byte = ((bbR>>1)*DHTOT + DIN + hglob)*8 + (bbR&1)*4
        uint32_t hoff = base + COMB_OFF +
                        (uint32_t)((((bbR>>1)*DHTOT + DIN + hglob)*8) + (bbR&1)*4);
        #pragma unroll
        for (uint32_t r = 0; r < CSZ; ++r){
            kAddr[r]  = mapa_u32(koff, r);
            hvAddr[r] = mapa_u32(hoff, r);
        }
    }

    const float4* pcol = &g_protoPack[dcD*6][rank*32 + plD];

    float cx = 0.f, hv = 0.f;

    __syncthreads();
    cl_arrive(); cl_wait();                       // init visible cluster-wide

    for (int t = 0; t < TSTEPS; ++t){
        __syncthreads();                          // x(t) stores visible locally

        // ---- cn2 (warps 0-3, one batch-pair each) ----
        if (tid < 128){
            int pr = tid >> 5, lane = tid & 31;
            u64 a = 0ull;
            #pragma unroll
            for (int j = 0; j < 12; ++j){
                u64 c = COMB[pr*DHTOT + lane + 32*j];
                a = ffma2(c, c, a);
            }
            #pragma unroll
            for (int off = 16; off; off >>= 1)
                a = add2(a, __shfl_xor_sync(0xffffffffu, a, off));
            if (lane == 0) CN[pr] = a;
        }

        // ---- dist partials: thread=(pl, dc), 24 d = 6 float4 rows ----
        {
            u64 a0 = 0ull, a1 = 0ull, a2 = 0ull, a3 = 0ull;
            const int d0base = dcD*24;
            #pragma unroll
            for (int j = 0; j < 6; ++j){
                float4 pv = pcol[j*NPROTO];
                int d0 = d0base + 4*j;
                u64 v0 = pk2(pv.x, pv.x), v1 = pk2(pv.y, pv.y);
                u64 v2 = pk2(pv.z, pv.z), v3 = pk2(pv.w, pv.w);
                #pragma unroll
                for (int pr = 0; pr < 4; ++pr){
                    const ulonglong2* c2 = reinterpret_cast<const ulonglong2*>(COMB + pr*DHTOT + d0);
                    ulonglong2 cA = c2[0];
                    ulonglong2 cB = c2[1];
                    u64 acc = (pr==0)?a0:(pr==1)?a1:(pr==2)?a2:a3;
                    acc = ffma2(cA.x, v0, acc);
                    acc = ffma2(cA.y, v1, acc);
                    acc = ffma2(cB.x, v2, acc);
                    acc = ffma2(cB.y, v3, acc);
                    if (pr==0) a0=acc; else if (pr==1) a1=acc; else if (pr==2) a2=acc; else a3=acc;
                }
            }
            PD[(dcD*4 + 0)*32 + plD] = a0;
            PD[(dcD*4 + 1)*32 + plD] = a1;
            PD[(dcD*4 + 2)*32 + plD] = a2;
            PD[(dcD*4 + 3)*32 + plD] = a3;
        }
        __syncthreads();                          // PD + CN ready

        // ---- k finish + cluster broadcast (threads 0..127) ----
        if (tid < 128){
            int pl = tid & 31, pr = tid >> 5;
            u64 dot = PD[(0*4 + pr)*32 + pl];
            #pragma unroll
            for (int dc = 1; dc < 16; ++dc)
                dot = add2(dot, PD[(dc*4 + pr)*32 + pl]);
            float d0, d1; upk2(dot, d0, d1);
            float c0, c1; upk2(CN[pr], c0, c1);
            float k0 = __expf(2.f*d0 - pn2v - c0);
            float k1 = __expf(2.f*d1 - pn2v - c1);
            u64 kk0 = pk2(k0, k0), kk1 = pk2(k1, k1);
            #pragma unroll
            for (int r = 0; r < CSZ; ++r){
                st_cl64(kAddr[r],     kk0);
                st_cl64(kAddr[r] + 8, kk1);
            }
        }
        cl_arrive(); cl_wait();                   // A: all k visible everywhere

        // ---- gate partial GEMM: thread=(hL, pc), 16 p's, 8 batches ----
        {
            u64 F0=0,F1=0,F2=0,F3=0,F4=0,F5=0,F6=0,F7=0;
            u64 G0=0,G1=0,G2=0,G3=0,G4=0,G5=0,G6=0,G7=0;
            const ulonglong2* wp = reinterpret_cast<const ulonglong2*>(WQ) + (pcG*16)*64 + hL;
            const ulonglong2* kp = KD2 + (pcG*16)*4;
            #pragma unroll 4
            for (int j = 0; j < 16; ++j){
                ulonglong2 w  = wp[j*64];
                ulonglong2 kA = kp[j*4 + 0];
                ulonglong2 kB = kp[j*4 + 1];
                ulonglong2 kC = kp[j*4 + 2];
                ulonglong2 kD_ = kp[j*4 + 3];
                F0 = ffma2(w.x, kA.x, F0);  G0 = ffma2(w.y, kA.x, G0);
                F1 = ffma2(w.x, kA.y, F1);  G1 = ffma2(w.y, kA.y, G1);
                F2 = ffma2(w.x, kB.x, F2);  G2 = ffma2(w.y, kB.x, G2);
                F3 = ffma2(w.x, kB.y, F3);  G3 = ffma2(w.y, kB.y, G3);
                F4 = ffma2(w.x, kC.x, F4);  G4 = ffma2(w.y, kC.x, G4);
                F5 = ffma2(w.x, kC.y, F5);  G5 = ffma2(w.y, kC.y, G5);
                F6 = ffma2(w.x, kD_.x, F6); G6 = ffma2(w.y, kD_.x, G6);
                F7 = ffma2(w.x, kD_.y, F7); G7 = ffma2(w.y, kD_.y, G7);
            }
            u64* pg = PG + (pcG*8)*2*64 + hL;
            pg[(0*2+0)*64] = F0; pg[(0*2+1)*64] = G0;
            pg[(1*2+0)*64] = F1; pg[(1*2+1)*64] = G1;
            pg[(2*2+0)*64] = F2; pg[(2*2+1)*64] = G2;
            pg[(3*2+0)*64] = F3; pg[(3*2+1)*64] = G3;
            pg[(4*2+0)*64] = F4; pg[(4*2+1)*64] = G4;
            pg[(5*2+0)*64] = F5; pg[(5*2+1)*64] = G5;
            pg[(6*2+0)*64] = F6; pg[(6*2+1)*64] = G6;
            pg[(7*2+0)*64] = F7; pg[(7*2+1)*64] = G7;
        }
        __syncthreads();                          // PG ready

        // ---- reduce + activations: thread=(hL, batch bbR) ----
        {
            u64 Fa = bFI, Ga = bGO;
            #pragma unroll
            for (int c = 0; c < 8; ++c){
                const u64* pg = PG + (c*8 + bbR)*2*64 + hL;
                Fa = add2(Fa, pg[0]);
                Ga = add2(Ga, pg[64]);
            }
            float fp, ip, gp, op;
            upk2(Fa, fp, ip); upk2(Ga, gp, op);
            float fv = sigmf(fp), iv = sigmf(ip), gv = tanhf_(gp), ov = sigmf(op);
            cx = fv*cx + iv*gv;
            hv = ov * tanhf_(cx);
            #pragma unroll
            for (int r = 0; r < CSZ; ++r) st_cl32(hvAddr[r], hv);
            out[((size_t)t*BSZ + bbase + bbR)*HID + hglob] = hv;
        }
        cl_arrive();                              // B arrive: hv stores released

        // ---- prefetch x(t+1) while peers finish (x-region is free) ----
        if (t + 1 < TSTEPS){
            const float* xb = x + ((size_t)(t+1)*BSZ + bbase)*DIN;
            #pragma unroll
            for (int i = 0; i < (NB*DIN)/NTHR; ++i){
                int idx = tid + i*NTHR;
                int b = idx >> 7, d = idx & (DIN-1);
                COMBF[(b >> 1)*DHTOT*2 + d*2 + (b & 1)] = __ldcg(&xb[idx]);
            }
        }
        cl_wait();                                // B wait: all hv visible
    }

    // ---- finals: hx, cx after outputs ----
    {
        const size_t TBH = (size_t)TSTEPS * BSZ * HID;
        const size_t BH  = (size_t)BSZ * HID;
        out[TBH + (size_t)(bbase + bbR)*HID + hglob] = hv;
        out[TBH + BH + (size_t)(bbase + bbR)*HID + hglob] = cx;
    }
}

extern "C" void kernel_launch(void* const* d_in, const int* in_sizes, int n_in,
                              void* d_out, int out_size){
    (void)in_sizes; (void)n_in; (void)out_size;
    const float* inputs = (const float*)d_in[0];
    const float* proto  = (const float*)d_in[1];
    const float* Wf     = (const float*)d_in[2];
    const float* bf     = (const float*)d_in[3];
    const float* Wi     = (const float*)d_in[4];
    const float* bi     = (const float*)d_in[5];
    const float* Wg     = (const float*)d_in[6];
    const float* bg     = (const float*)d_in[7];
    const float* Wo     = (const float*)d_in[8];
    const float* bo     = (const float*)d_in[9];
    float* out = (float*)d_out;

    cudaFuncSetAttribute(qlstm_kernel,
                         cudaFuncAttributeMaxDynamicSharedMemorySize, SMEM_TOTAL);

    pack_kernel<<<(HID*NPROTO + 511)/512, 512>>>(proto, Wf, Wi, Wg, Wo);
    qlstm_kernel<<<NCTA, NTHR, SMEM_TOTAL>>>(inputs, bf, bi, bg, bo, out);
}

// round 4
// speedup vs baseline: 1.3145x; 1.3145x over previous
#include <cuda_runtime.h>
#include <cstdint>

#define TSTEPS 512
#define BSZ    256
#define DIN    128
#define HID    256
#define NPROTO 128
#define DHTOT  384
#define NB     8            // batches per cluster
#define CSZ    4            // CTAs per cluster
#define NTHR   512
#define NCTA   128

__device__ float4 g_Wpack[NPROTO][HID];          // [p][h] = {wf, wi, wg, wo}
__device__ float4 g_protoPack[DHTOT/4][NPROTO];  // [q][p] = proto[p][4q..4q+3]
__device__ float  g_pn2[NPROTO];

typedef unsigned long long u64;

// ---------------- smem layout (bytes) ----------------
// PROT: [24 q][128 p] float4                    49152   (CTA's d-slice of prototypes)
// PG  : [8 pc][8 b][2 fi][64 h] u64             65536
// KD  : [128 p][10] u64 (pad 8->10, {k,k} dup)  10240
// DOT : [2 buf][4 r][4 pr][128 p] u64           32768
// CN2 : [2 buf][4 r][4 pr] u64                    256
// CMB : [4 pr][96 d] u64 ({b_even,b_odd})        3072
#define PROT_OFF 0
#define PG_OFF   49152
#define KD_OFF   114688
#define DOT_OFF  124928
#define CN2_OFF  157696
#define CMB_OFF  157952
#define SMEM_TOTAL 161024

__device__ __forceinline__ u64 pk2(float lo, float hi){
    u64 r; asm("mov.b64 %0, {%1,%2};" : "=l"(r) : "f"(lo), "f"(hi)); return r;
}
__device__ __forceinline__ void upk2(u64 v, float& lo, float& hi){
    asm("mov.b64 {%0,%1}, %2;" : "=f"(lo), "=f"(hi) : "l"(v));
}
__device__ __forceinline__ u64 ffma2(u64 a, u64 b, u64 c){
    u64 d; asm("fma.rn.f32x2 %0, %1, %2, %3;" : "=l"(d) : "l"(a), "l"(b), "l"(c)); return d;
}
__device__ __forceinline__ u64 add2(u64 a, u64 b){
    u64 d; asm("add.rn.f32x2 %0, %1, %2;" : "=l"(d) : "l"(a), "l"(b)); return d;
}
__device__ __forceinline__ float sigmf(float x){
    return __fdividef(1.f, 1.f + __expf(-x));
}
__device__ __forceinline__ float tanhf_(float x){
    return 1.f - __fdividef(2.f, __expf(2.f*x) + 1.f);
}
__device__ __forceinline__ uint32_t smem_u32(const void* p){
    uint32_t a;
    asm("{ .reg .u64 t; cvta.to.shared.u64 t, %1; cvt.u32.u64 %0, t; }" : "=r"(a) : "l"(p));
    return a;
}
__device__ __forceinline__ uint32_t ctarank(){
    uint32_t r; asm("mov.u32 %0, %%cluster_ctarank;" : "=r"(r)); return r;
}
__device__ __forceinline__ uint32_t mapa_u32(uint32_t local, uint32_t rank){
    uint32_t r; asm("mapa.shared::cluster.u32 %0, %1, %2;" : "=r"(r) : "r"(local), "r"(rank));
    return r;
}
__device__ __forceinline__ void st_cl64(uint32_t addr, u64 v){
    asm volatile("st.shared::cluster.b64 [%0], %1;" :: "r"(addr), "l"(v) : "memory");
}
__device__ __forceinline__ void cl_arrive(){
    asm volatile("barrier.cluster.arrive.aligned;" ::: "memory");
}
__device__ __forceinline__ void cl_wait(){
    asm volatile("barrier.cluster.wait.aligned;"   ::: "memory");
}
__device__ __forceinline__ u64 shfl_xor64(u64 v, int off){
    uint32_t lo = (uint32_t)v, hi = (uint32_t)(v >> 32);
    lo = __shfl_xor_sync(0xffffffffu, lo, off);
    hi = __shfl_xor_sync(0xffffffffu, hi, off);
    return ((u64)hi << 32) | lo;
}

__global__ void pack_kernel(const float* __restrict__ proto,
                            const float* __restrict__ Wf, const float* __restrict__ Wi,
                            const float* __restrict__ Wg, const float* __restrict__ Wo){
    int idx = blockIdx.x * blockDim.x + threadIdx.x;
    if (idx < HID*NPROTO){
        int h = idx >> 7, pp = idx & (NPROTO-1);
        g_Wpack[pp][h] = make_float4(Wf[idx], Wi[idx], Wg[idx], Wo[idx]);
    }
    if (idx < (DHTOT/4)*NPROTO){
        int q = idx >> 7, pp = idx & (NPROTO-1);
        const float* pr = proto + pp*DHTOT + 4*q;
        g_protoPack[q][pp] = make_float4(pr[0], pr[1], pr[2], pr[3]);
    }
    if (idx < NPROTO){
        float s = 0.f;
        for (int d = 0; d < DHTOT; ++d){ float v = proto[idx*DHTOT + d]; s = fmaf(v, v, s); }
        g_pn2[idx] = s;
    }
}

extern __shared__ char sm[];

__global__ void __cluster_dims__(CSZ,1,1) __launch_bounds__(NTHR, 1)
qlstm_kernel(const float* __restrict__ x,
             const float* __restrict__ bf, const float* __restrict__ bi,
             const float* __restrict__ bg, const float* __restrict__ bo,
             float* __restrict__ out){
    const int tid  = threadIdx.x;
    const uint32_t rank = ctarank();
    const int bbase = (blockIdx.x >> 2) * NB;
    const uint32_t base = smem_u32(sm);

    float4* PROT = reinterpret_cast<float4*>(sm + PROT_OFF);  // [q][p]
    u64*    PGp  = reinterpret_cast<u64*>(sm + PG_OFF);
    u64*    KD   = reinterpret_cast<u64*>(sm + KD_OFF);       // [p][10], {k,k} dup
    const ulonglong2* KDv2 = reinterpret_cast<const ulonglong2*>(sm + KD_OFF);
    u64*    DOT  = reinterpret_cast<u64*>(sm + DOT_OFF);
    u64*    CN2  = reinterpret_cast<u64*>(sm + CN2_OFF);
    u64*    CMB  = reinterpret_cast<u64*>(sm + CMB_OFF);      // [pr][96 d]
    float*  CMBF = reinterpret_cast<float*>(sm + CMB_OFF);

    // ---------- per-thread role constants ----------
    const int pD  = tid & 127;          // dist/k: prototype index
    const int prD = tid >> 7;           // dist/k: batch-pair (0..3)
    const int hL  = tid & 63;           // gate/reduce: local h
    const int pc  = tid >> 6;           // gate: p-chunk (0..7)
    const int bR  = tid >> 6;           // reduce: batch (0..7)
    const int hglob = rank*64 + hL;

    // ---------- preamble ----------
    // prototype d-slice -> smem, chunk q of slice: q<8 -> x-chunk 8*rank+q,
    // else h-chunk 32 + 16*rank + (q-8)
    #pragma unroll
    for (int i = 0; i < 6; ++i){
        int idx = tid + i*NTHR;         // 0..3071
        int q = idx >> 7, p = idx & 127;
        int Q = (q < 8) ? (8*(int)rank + q) : (32 + 16*(int)rank + (q - 8));
        PROT[q*128 + p] = g_protoPack[Q][p];
    }
    // persistent register weights: thread (hL, pc) holds p = pc*16 .. pc*16+15
    u64 wFI[16], wGO[16];
    #pragma unroll
    for (int j = 0; j < 16; ++j){
        float4 w = g_Wpack[pc*16 + j][hglob];
        wFI[j] = pk2(w.x, w.y);
        wGO[j] = pk2(w.z, w.w);
    }
    // zero hv region of CMB (slots 32..95 per pair)
    if (tid < 256){
        int pr = tid >> 6, sl = tid & 63;
        CMB[pr*96 + 32 + sl] = 0ull;
    }
    // load x(0) slice: d = 32*rank + dl
    if (tid < 256){
        int b = tid >> 5, dl = tid & 31;
        CMBF[((b >> 1)*96 + dl)*2 + (b & 1)] =
            __ldcg(&x[((size_t)0*BSZ + bbase + b)*DIN + rank*32 + dl]);
    }

    const u64 bFI = pk2(bf[hglob], bi[hglob]);
    const u64 bGO = pk2(bg[hglob], bo[hglob]);
    const float pn2v = g_pn2[pD];

    // DSMEM addresses: my dot-partial slot and cn2 slot in every rank
    uint32_t dotAddr[CSZ], cnAddr[CSZ];
    {
        uint32_t dOff = base + DOT_OFF + (uint32_t)((((rank*4) + prD)*128 + pD)*8);
        uint32_t cOff = base + CN2_OFF + (uint32_t)((rank*4 + (tid >> 5))*8);  // cn2 role: pr=tid>>5 (tid<128)
        #pragma unroll
        for (uint32_t r = 0; r < CSZ; ++r){
            dotAddr[r] = mapa_u32(dOff, r);
            cnAddr[r]  = mapa_u32(cOff, r);
        }
    }

    float cx = 0.f, hv = 0.f;

    __syncthreads();
    cl_arrive(); cl_wait();             // init visible cluster-wide

    for (int t = 0; t < TSTEPS; ++t){
        const uint32_t bufDot = (uint32_t)(t & 1) * 16384u;   // DOT buf byte stride
        const uint32_t bufCn  = (uint32_t)(t & 1) * 128u;
        const int      bufU   = (t & 1) * 2048;               // DOT buf u64 stride
        const int      bufC   = (t & 1) * 16;

        __syncthreads();                // S1: x(t) + hv(t-1) visible in CMB

        // ---- dist partial: thread=(pD, prD), 96 d slice ----
        {
            u64 accA = 0ull, accB = 0ull;
            const float4* pp = PROT + pD;
            const u64*    cb = CMB + prD*96;
            #pragma unroll
            for (int q = 0; q < 24; ++q){
                float4 pv = pp[q*128];
                ulonglong2 cA = *reinterpret_cast<const ulonglong2*>(cb + 4*q);
                ulonglong2 cB = *reinterpret_cast<const ulonglong2*>(cb + 4*q + 2);
                accA = ffma2(cA.x, pk2(pv.x, pv.x), accA);
                accB = ffma2(cA.y, pk2(pv.y, pv.y), accB);
                accA = ffma2(cB.x, pk2(pv.z, pv.z), accA);
                accB = ffma2(cB.y, pk2(pv.w, pv.w), accB);
            }
            u64 acc = add2(accA, accB);
            #pragma unroll
            for (int r = 0; r < CSZ; ++r) st_cl64(dotAddr[r] + bufDot, acc);
        }

        // ---- cn2 partial over slice (warps 0-3: pr = tid>>5) ----
        if (tid < 128){
            int lane = tid & 31;
            const u64* cb = CMB + (tid >> 5)*96;
            u64 a = 0ull;
            u64 c0 = cb[lane], c1 = cb[lane+32], c2 = cb[lane+64];
            a = ffma2(c0, c0, a);
            a = ffma2(c1, c1, a);
            a = ffma2(c2, c2, a);
            #pragma unroll
            for (int off = 16; off; off >>= 1)
                a = add2(a, shfl_xor64(a, off));
            if (lane == 0){
                #pragma unroll
                for (int r = 0; r < CSZ; ++r) st_cl64(cnAddr[r] + bufCn, a);
            }
        }
        __syncthreads();                // S2: all local warps done reading CMB-x / writing partials

        cl_arrive();                    // release my partials

        // ---- prefetch x(t+1) into CMB-x while peers finish ----
        if (t + 1 < TSTEPS && tid < 256){
            int b = tid >> 5, dl = tid & 31;
            CMBF[((b >> 1)*96 + dl)*2 + (b & 1)] =
                __ldcg(&x[((size_t)(t+1)*BSZ + bbase + b)*DIN + rank*32 + dl]);
        }
        cl_wait();                      // acquire all ranks' partials

        // ---- k: thread=(pD, prD), reduce 4 rank-partials, 2 exps ----
        {
            const u64* db = DOT + bufU;
            u64 ds =        db[(0*4 + prD)*128 + pD];
            ds = add2(ds,   db[(1*4 + prD)*128 + pD]);
            ds = add2(ds,   db[(2*4 + prD)*128 + pD]);
            ds = add2(ds,   db[(3*4 + prD)*128 + pD]);
            const u64* cn = CN2 + bufC;
            u64 cs = add2(add2(cn[0*4 + prD], cn[1*4 + prD]),
                          add2(cn[2*4 + prD], cn[3*4 + prD]));
            float d0, d1, c0, c1;
            upk2(ds, d0, d1); upk2(cs, c0, c1);
            float k0 = __expf(2.f*d0 - pn2v - c0);
            float k1 = __expf(2.f*d1 - pn2v - c1);
            ulonglong2 kk; kk.x = pk2(k0, k0); kk.y = pk2(k1, k1);
            *reinterpret_cast<ulonglong2*>(KD + pD*10 + 2*prD) = kk;
        }
        __syncthreads();                // S3: KD ready

        // ---- gate GEMM from register weights: thread=(hL, pc), 2 b-half passes ----
        #pragma unroll
        for (int bh = 0; bh < 2; ++bh){
            u64 F0=0,F1=0,F2=0,F3=0,G0=0,G1=0,G2=0,G3=0;
            #pragma unroll
            for (int j = 0; j < 16; ++j){
                int p = pc*16 + j;
                ulonglong2 kA = KDv2[p*5 + 2*bh];       // {k,k} for b=4bh, 4bh+1
                ulonglong2 kB = KDv2[p*5 + 2*bh + 1];   // {k,k} for b=4bh+2, 4bh+3
                F0 = ffma2(wFI[j], kA.x, F0);  G0 = ffma2(wGO[j], kA.x, G0);
                F1 = ffma2(wFI[j], kA.y, F1);  G1 = ffma2(wGO[j], kA.y, G1);
                F2 = ffma2(wFI[j], kB.x, F2);  G2 = ffma2(wGO[j], kB.x, G2);
                F3 = ffma2(wFI[j], kB.y, F3);  G3 = ffma2(wGO[j], kB.y, G3);
            }
            u64* pg = PGp + ((pc*8 + bh*4)*2)*64 + hL;
            pg[0]   = F0; pg[64]  = G0;
            pg[128] = F1; pg[192] = G1;
            pg[256] = F2; pg[320] = G2;
            pg[384] = F3; pg[448] = G3;
        }
        __syncthreads();                // S4: PG ready

        // ---- reduce + activations: thread=(hL, bR) ----
        {
            u64 Fa = bFI, Ga = bGO;
            #pragma unroll
            for (int c = 0; c < 8; ++c){
                Fa = add2(Fa, PGp[((c*8 + bR)*2 + 0)*64 + hL]);
                Ga = add2(Ga, PGp[((c*8 + bR)*2 + 1)*64 + hL]);
            }
            float fp, ip, gp, op;
            upk2(Fa, fp, ip); upk2(Ga, gp, op);
            float fv = sigmf(fp), iv = sigmf(ip), gv = tanhf_(gp), ov = sigmf(op);
            cx = fv*cx + iv*gv;
            hv = ov * tanhf_(cx);
            // hv -> local CMB h-slot (this CTA's own h-quarter IS its d-slice)
            CMBF[((bR >> 1)*96 + 32 + hL)*2 + (bR & 1)] = hv;
            out[((size_t)t*BSZ + bbase + bR)*HID + hglob] = hv;
        }
        // loop-top S1 orders hv/x before next dist; DOT double-buffer + the
        // single cluster barrier handles cross-CTA WAR (a CTA can't pass two
        // barriers without every peer passing one).
    }

    // ---- finals: hx, cx appended after outputs ----
    {
        const size_t TBH = (size_t)TSTEPS * BSZ * HID;
        const size_t BH  = (size_t)BSZ * HID;
        out[TBH + (size_t)(bbase + bR)*HID + hglob] = hv;
        out[TBH + BH + (size_t)(bbase + bR)*HID + hglob] = cx;
    }
}

extern "C" void kernel_launch(void* const* d_in, const int* in_sizes, int n_in,
                              void* d_out, int out_size){
    (void)in_sizes; (void)n_in; (void)out_size;
    const float* inputs = (const float*)d_in[0];
    const float* proto  = (const float*)d_in[1];
    const float* Wf     = (const float*)d_in[2];
    const float* bf     = (const float*)d_in[3];
    const float* Wi     = (const float*)d_in[4];
    const float* bi     = (const float*)d_in[5];
    const float* Wg     = (const float*)d_in[6];
    const float* bg     = (const float*)d_in[7];
    const float* Wo     = (const float*)d_in[8];
    const float* bo     = (const float*)d_in[9];
    float* out = (float*)d_out;

    cudaFuncSetAttribute(qlstm_kernel,
                         cudaFuncAttributeMaxDynamicSharedMemorySize, SMEM_TOTAL);

    pack_kernel<<<(HID*NPROTO + 511)/512, 512>>>(proto, Wf, Wi, Wg, Wo);
    qlstm_kernel<<<NCTA, NTHR, SMEM_TOTAL>>>(inputs, bf, bi, bg, bo, out);
}